// round 10
// baseline (speedup 1.0000x reference)
#include <cuda_runtime.h>
#include <cuda_fp16.h>
#include <cstdint>

#define B_DIM 2048
#define M_DIM 64
#define F_DIM 512
#define U_DIM 512
#define LDX (M_DIM * F_DIM)
#define LDO (M_DIM * U_DIM)

#define BM 128
#define BN 128
#define BK 32
#define THREADS 256            // 8 warps: 4 (M) x 2 (N), warp tile 32x64
#define KITERS (F_DIM / BK)    // 16

#define SROW 40                              // halves per smem row (80 B): conflict-free LDSM
#define ROWB (SROW * 2)                      // 80 bytes
#define TILE_BYTES (128 * ROWB)              // 10240 B per A or B tile
#define STAGE_BYTES (2 * TILE_BYTES)         // 20480 B
#define STAGES 4
#define DYN_SMEM (STAGES * STAGE_BYTES)      // 81920 B -> 2 CTAs/SM

__device__ __half g_Wh[(size_t)M_DIM * F_DIM * U_DIM];   // W^T fp16: [m][u][k]
__device__ __half g_Xh[(size_t)B_DIM * M_DIM * F_DIM];   // x fp16:  [b][m][f]

// ---------------- helpers ----------------
static __device__ __forceinline__ uint32_t cvta_smem(const void* p) {
    uint32_t a;
    asm("{ .reg .u64 t; cvta.to.shared.u64 t, %1; cvt.u32.u64 %0, t; }" : "=r"(a) : "l"(p));
    return a;
}
static __device__ __forceinline__ void cp_async16(uint32_t smem_addr, const void* gptr) {
    asm volatile("cp.async.cg.shared.global [%0], [%1], 16;" :: "r"(smem_addr), "l"(gptr) : "memory");
}
static __device__ __forceinline__ void cp_commit() {
    asm volatile("cp.async.commit_group;" ::: "memory");
}
template <int N>
static __device__ __forceinline__ void cp_wait() {
    asm volatile("cp.async.wait_group %0;" :: "n"(N) : "memory");
}
static __device__ __forceinline__ void ldsm_x4(uint32_t addr, uint32_t* r) {
    asm volatile("ldmatrix.sync.aligned.m8n8.x4.shared.b16 {%0,%1,%2,%3}, [%4];"
                 : "=r"(r[0]), "=r"(r[1]), "=r"(r[2]), "=r"(r[3]) : "r"(addr));
}
static __device__ __forceinline__ void mma_f16(float* c, const uint32_t* a, const uint32_t* b) {
    asm volatile(
        "mma.sync.aligned.m16n8k16.row.col.f32.f16.f16.f32 "
        "{%0,%1,%2,%3}, {%4,%5,%6,%7}, {%8,%9}, {%0,%1,%2,%3};"
        : "+f"(c[0]), "+f"(c[1]), "+f"(c[2]), "+f"(c[3])
        : "r"(a[0]), "r"(a[1]), "r"(a[2]), "r"(a[3]), "r"(b[0]), "r"(b[1]));
}

// ---------------- prep 1: x -> fp16 (same layout) ----------------
__global__ void convert_x_kernel(const float4* __restrict__ xin) {
    const size_t idx = (size_t)blockIdx.x * blockDim.x + threadIdx.x;  // 8 floats each
    float4 v0 = xin[idx * 2], v1 = xin[idx * 2 + 1];
    __half2 h0 = __floats2half2_rn(v0.x, v0.y);
    __half2 h1 = __floats2half2_rn(v0.z, v0.w);
    __half2 h2 = __floats2half2_rn(v1.x, v1.y);
    __half2 h3 = __floats2half2_rn(v1.z, v1.w);
    uint4 o;
    o.x = *(uint32_t*)&h0; o.y = *(uint32_t*)&h1;
    o.z = *(uint32_t*)&h2; o.w = *(uint32_t*)&h3;
    reinterpret_cast<uint4*>(g_Xh)[idx] = o;
}

// ---------------- prep 2: W transpose + fp16: g_Wh[m][u][k] = (half)W[m][k][u] ----------------
__global__ void transpose_W_kernel(const float* __restrict__ W) {
    __shared__ float t[32][33];
    const int m = blockIdx.z;
    const int u0 = blockIdx.x * 32, k0 = blockIdx.y * 32;
    const int tx = threadIdx.x, ty = threadIdx.y;
    const float* Wm = W + (size_t)m * F_DIM * U_DIM;
    __half* Wtm = g_Wh + (size_t)m * F_DIM * U_DIM;
#pragma unroll
    for (int i = 0; i < 32; i += 8)
        t[ty + i][tx] = Wm[(size_t)(k0 + ty + i) * U_DIM + u0 + tx];
    __syncthreads();
#pragma unroll
    for (int i = 0; i < 32; i += 8)
        Wtm[(size_t)(u0 + ty + i) * F_DIM + k0 + tx] = __float2half_rn(t[tx][ty + i]);
}

// ---------------- main GEMM: fp16 mma.sync, ldmatrix feeds, 4-stage cp.async ----------------
__global__ __launch_bounds__(THREADS, 2)
void pd_mma_f16(const float* __restrict__ bias,
                float* __restrict__ out) {
    extern __shared__ __align__(16) char smem[];
    const uint32_t smemAddr = cvta_smem(smem);

    const int tid  = threadIdx.x;
    const int wid  = tid >> 5;
    const int lane = tid & 31;
    const int warpM = wid >> 1;         // 0..3
    const int warpN = wid & 1;          // 0..1
    const int g = lane >> 2;            // groupID
    const int t = lane & 3;             // thread-in-group
    const int quad = lane >> 3;         // ldmatrix address quad
    const int rl   = lane & 7;
    const int rot  = wid & 1;           // ks rotation: desync LDSM bursts

    const int bn = blockIdx.x, bm = blockIdx.y, m = blockIdx.z;
    const int rowBase = bm * BM;
    const int colBase = bn * BN;

    const __half* Xm  = g_Xh + (size_t)m * F_DIM;
    const __half* Wtm = g_Wh + (size_t)m * F_DIM * U_DIM;

    // ---- staging coords: per tile 128 rows x 4 chunks(16B); 2 A + 2 B chunks per thread ----
    const __half* aSrc[2]; const __half* bSrc[2];
    uint32_t dstOff[2];
#pragma unroll
    for (int j = 0; j < 2; ++j) {
        int e = j * 256 + tid;          // 0..511
        int r = e >> 2, c = e & 3;
        aSrc[j] = Xm  + (size_t)(rowBase + r) * LDX + c * 8;
        bSrc[j] = Wtm + (size_t)(colBase + r) * F_DIM + c * 8;
        dstOff[j] = (uint32_t)(r * ROWB + c * 16);
    }

    auto issue_loads = [&](uint32_t stageOff, int k0) {
        uint32_t base = smemAddr + stageOff;
#pragma unroll
        for (int j = 0; j < 2; ++j)
            cp_async16(base + dstOff[j], aSrc[j] + k0);
#pragma unroll
        for (int j = 0; j < 2; ++j)
            cp_async16(base + TILE_BYTES + dstOff[j], bSrc[j] + k0);
        cp_commit();
    };

    // ---- ldmatrix per-lane offsets ----
    // A x4 quads: row = (q&1)*8 + rl, kbyte = (q>>1)*16  -> regs a0..a3 canonical
    const uint32_t aLaneOff =
        (uint32_t)((warpM * 32 + (quad & 1) * 8 + rl) * ROWB + (quad >> 1) * 16);
    // B x4 quads: row(n) = (q>>1)*8 + rl, kbyte = (q&1)*16 -> [g0 k0][g0 k8][g1 k0][g1 k8]
    const uint32_t bLaneOff =
        (uint32_t)((warpN * 64 + (quad >> 1) * 8 + rl) * ROWB + (quad & 1) * 16) + TILE_BYTES;

    float acc[2][8][4];
#pragma unroll
    for (int mi = 0; mi < 2; ++mi)
#pragma unroll
        for (int ni = 0; ni < 8; ++ni)
#pragma unroll
            for (int c = 0; c < 4; ++c) acc[mi][ni][c] = 0.0f;

    // ---- prologue: 3 stages in flight ----
    issue_loads(0, 0);
    issue_loads(STAGE_BYTES, BK);
    issue_loads(2 * STAGE_BYTES, 2 * BK);

    uint32_t compOff  = 0;
    uint32_t issueOff = 3 * STAGE_BYTES;

    for (int it = 0; it < KITERS; ++it) {
        // Pending: stages it, it+1, it+2. wait<2> -> stage `it` arrived.
        cp_wait<2>();
        // Barrier: stage it visible to all; all warps done with stage it-1
        // (its buffer (it+3)%4 is re-filled below).
        __syncthreads();

        const uint32_t aA = smemAddr + compOff + aLaneOff;
        const uint32_t bA = smemAddr + compOff + bLaneOff;

#pragma unroll
        for (int kk = 0; kk < 2; ++kk) {
            const int ks = (kk + rot) & 1;           // warp-parity rotated k16-chunk
            const uint32_t ko = (uint32_t)(ks * 32); // 16 halves = 32 B

            uint32_t af[2][4], bf[4][4];
            ldsm_x4(aA + ko,        af[0]);
            ldsm_x4(aA + 1280 + ko, af[1]);          // +16 rows * 80 B
            ldsm_x4(bA + ko,        bf[0]);          // n-groups 0,1
            ldsm_x4(bA + 1280 + ko, bf[1]);          // n-groups 2,3
#pragma unroll
            for (int p = 0; p < 2; ++p) {
#pragma unroll
                for (int mi = 0; mi < 2; ++mi) {
                    mma_f16(acc[mi][2 * p],     af[mi], &bf[p][0]);
                    mma_f16(acc[mi][2 * p + 1], af[mi], &bf[p][2]);
                }
            }
            ldsm_x4(bA + 2 * 1280 + ko, bf[2]);      // n-groups 4,5
            ldsm_x4(bA + 3 * 1280 + ko, bf[3]);      // n-groups 6,7

            if (kk == 0) {
                if (it + 3 < KITERS) issue_loads(issueOff, (it + 3) * BK);
                else                 cp_commit();    // keep group accounting aligned
            }

#pragma unroll
            for (int p = 2; p < 4; ++p) {
#pragma unroll
                for (int mi = 0; mi < 2; ++mi) {
                    mma_f16(acc[mi][2 * p],     af[mi], &bf[p][0]);
                    mma_f16(acc[mi][2 * p + 1], af[mi], &bf[p][2]);
                }
            }
        }

        compOff += STAGE_BYTES;  if (compOff  == DYN_SMEM) compOff  = 0;
        issueOff += STAGE_BYTES; if (issueOff == DYN_SMEM) issueOff = 0;
    }

    // ---------------- epilogue: bias + relu + store ----------------
    const float* bm_bias = bias + (size_t)m * U_DIM + colBase + warpN * 64;
#pragma unroll
    for (int mi = 0; mi < 2; ++mi) {
        const int r0 = rowBase + warpM * 32 + mi * 16 + g;
        float* o0 = out + (size_t)r0 * LDO + (size_t)m * U_DIM + colBase + warpN * 64;
        float* o1 = o0 + (size_t)8 * LDO;
#pragma unroll
        for (int ni = 0; ni < 8; ++ni) {
            const int c = ni * 8 + t * 2;
            const float b0 = bm_bias[c], b1 = bm_bias[c + 1];
            float2 v0, v1;
            v0.x = fmaxf(acc[mi][ni][0] + b0, 0.0f);
            v0.y = fmaxf(acc[mi][ni][1] + b1, 0.0f);
            v1.x = fmaxf(acc[mi][ni][2] + b0, 0.0f);
            v1.y = fmaxf(acc[mi][ni][3] + b1, 0.0f);
            *(float2*)(o0 + c) = v0;
            *(float2*)(o1 + c) = v1;
        }
    }
}

// ---------------- launch ----------------
extern "C" void kernel_launch(void* const* d_in, const int* in_sizes, int n_in,
                              void* d_out, int out_size) {
    const float* x    = (const float*)d_in[0];
    const float* W    = (const float*)d_in[1];
    const float* bias = (const float*)d_in[2];
    float* out        = (float*)d_out;

    // prep: x -> fp16 (67108864 elems / 8 per thread / 256 per block)
    convert_x_kernel<<<32768, 256>>>((const float4*)x);
    // prep: W -> W^T fp16
    dim3 tg(U_DIM / 32, F_DIM / 32, M_DIM);   // (16,16,64)
    transpose_W_kernel<<<tg, dim3(32, 8)>>>(W);

    cudaFuncSetAttribute(pd_mma_f16, cudaFuncAttributeMaxDynamicSharedMemorySize, DYN_SMEM);
    dim3 grid(U_DIM / BN, B_DIM / BM, M_DIM);  // (4,16,64) = 4096 CTAs
    pd_mma_f16<<<grid, THREADS, DYN_SMEM>>>(bias, out);
}

// round 11
// speedup vs baseline: 1.5110x; 1.5110x over previous
#include <cuda_runtime.h>
#include <cuda_fp16.h>
#include <cstdint>

#define B_DIM 2048
#define M_DIM 64
#define F_DIM 512
#define U_DIM 512
#define LDX (M_DIM * F_DIM)
#define LDO (M_DIM * U_DIM)

#define BM 128
#define BN 128
#define BK 64
#define THREADS 256            // 8 warps: 4 (M) x 2 (N), warp tile 32x64
#define KITERS (F_DIM / BK)    // 8

#define ROWB 144                             // bytes per smem row (64 halves + 8 pad)
#define TILE_BYTES (128 * ROWB)              // 18432 B per A or B tile
#define STAGE_BYTES (2 * TILE_BYTES)         // 36864 B
#define STAGES 3
#define DYN_SMEM (STAGES * STAGE_BYTES)      // 110592 B -> 2 CTAs/SM

__device__ __half g_Wh[(size_t)M_DIM * F_DIM * U_DIM];   // W^T fp16: [m][u][k]
__device__ __half g_Xh[(size_t)B_DIM * M_DIM * F_DIM];   // x fp16:  [b][m][f]

// ---------------- helpers ----------------
static __device__ __forceinline__ uint32_t cvta_smem(const void* p) {
    uint32_t a;
    asm("{ .reg .u64 t; cvta.to.shared.u64 t, %1; cvt.u32.u64 %0, t; }" : "=r"(a) : "l"(p));
    return a;
}
static __device__ __forceinline__ void cp_async16(uint32_t smem_addr, const void* gptr) {
    asm volatile("cp.async.cg.shared.global [%0], [%1], 16;" :: "r"(smem_addr), "l"(gptr) : "memory");
}
static __device__ __forceinline__ void cp_commit() {
    asm volatile("cp.async.commit_group;" ::: "memory");
}
template <int N>
static __device__ __forceinline__ void cp_wait() {
    asm volatile("cp.async.wait_group %0;" :: "n"(N) : "memory");
}
static __device__ __forceinline__ void ldsm_x4(uint32_t addr, uint32_t* r) {
    asm volatile("ldmatrix.sync.aligned.m8n8.x4.shared.b16 {%0,%1,%2,%3}, [%4];"
                 : "=r"(r[0]), "=r"(r[1]), "=r"(r[2]), "=r"(r[3]) : "r"(addr));
}
static __device__ __forceinline__ void mma_f16(float* c, const uint32_t* a, const uint32_t* b) {
    asm volatile(
        "mma.sync.aligned.m16n8k16.row.col.f32.f16.f16.f32 "
        "{%0,%1,%2,%3}, {%4,%5,%6,%7}, {%8,%9}, {%0,%1,%2,%3};"
        : "+f"(c[0]), "+f"(c[1]), "+f"(c[2]), "+f"(c[3])
        : "r"(a[0]), "r"(a[1]), "r"(a[2]), "r"(a[3]), "r"(b[0]), "r"(b[1]));
}

// ---------------- prep 1: x -> fp16 (same layout) ----------------
__global__ void convert_x_kernel(const float4* __restrict__ xin) {
    const size_t idx = (size_t)blockIdx.x * blockDim.x + threadIdx.x;  // 8 floats each
    float4 v0 = xin[idx * 2], v1 = xin[idx * 2 + 1];
    __half2 h0 = __floats2half2_rn(v0.x, v0.y);
    __half2 h1 = __floats2half2_rn(v0.z, v0.w);
    __half2 h2 = __floats2half2_rn(v1.x, v1.y);
    __half2 h3 = __floats2half2_rn(v1.z, v1.w);
    uint4 o;
    o.x = *(uint32_t*)&h0; o.y = *(uint32_t*)&h1;
    o.z = *(uint32_t*)&h2; o.w = *(uint32_t*)&h3;
    reinterpret_cast<uint4*>(g_Xh)[idx] = o;
}

// ---------------- prep 2: W transpose + fp16: g_Wh[m][u][k] = (half)W[m][k][u] ----------------
__global__ void transpose_W_kernel(const float* __restrict__ W) {
    __shared__ float t[32][33];
    const int m = blockIdx.z;
    const int u0 = blockIdx.x * 32, k0 = blockIdx.y * 32;
    const int tx = threadIdx.x, ty = threadIdx.y;
    const float* Wm = W + (size_t)m * F_DIM * U_DIM;
    __half* Wtm = g_Wh + (size_t)m * F_DIM * U_DIM;
#pragma unroll
    for (int i = 0; i < 32; i += 8)
        t[ty + i][tx] = Wm[(size_t)(k0 + ty + i) * U_DIM + u0 + tx];
    __syncthreads();
#pragma unroll
    for (int i = 0; i < 32; i += 8)
        Wtm[(size_t)(u0 + ty + i) * F_DIM + k0 + tx] = __float2half_rn(t[tx][ty + i]);
}

// ---------------- main GEMM: fp16 mma.sync, BK=64, 3-stage cp.async ----------------
__global__ __launch_bounds__(THREADS, 2)
void pd_mma_f16(const float* __restrict__ bias,
                float* __restrict__ out) {
    extern __shared__ __align__(16) char smem[];
    const uint32_t smemAddr = cvta_smem(smem);

    const int tid  = threadIdx.x;
    const int wid  = tid >> 5;
    const int lane = tid & 31;
    const int warpM = wid >> 1;         // 0..3
    const int warpN = wid & 1;          // 0..1
    const int g = lane >> 2;            // groupID
    const int t = lane & 3;             // thread-in-group
    const int quad = lane >> 3;         // ldmatrix address quad
    const int rl   = lane & 7;
    const int rot  = (wid & 1) * 2;     // ks rotation: desync LDSM bursts

    const int bn = blockIdx.x, bm = blockIdx.y, m = blockIdx.z;
    const int rowBase = bm * BM;
    const int colBase = bn * BN;

    const __half* Xm  = g_Xh + (size_t)m * F_DIM;
    const __half* Wtm = g_Wh + (size_t)m * F_DIM * U_DIM;

    // ---- staging coords: per tile 128 rows x 8 chunks(16B); 4 A + 4 B chunks per thread ----
    const __half* aSrc[4]; const __half* bSrc[4];
    uint32_t dstOff[4];
#pragma unroll
    for (int j = 0; j < 4; ++j) {
        int e = j * 256 + tid;          // 0..1023
        int r = e >> 3, c = e & 7;
        aSrc[j] = Xm  + (size_t)(rowBase + r) * LDX + c * 8;
        bSrc[j] = Wtm + (size_t)(colBase + r) * F_DIM + c * 8;
        dstOff[j] = (uint32_t)(r * ROWB + c * 16);
    }

    auto issue_A = [&](uint32_t stageOff, int k0) {
        uint32_t base = smemAddr + stageOff;
#pragma unroll
        for (int j = 0; j < 4; ++j)
            cp_async16(base + dstOff[j], aSrc[j] + k0);
    };
    auto issue_B = [&](uint32_t stageOff, int k0) {
        uint32_t base = smemAddr + stageOff + TILE_BYTES;
#pragma unroll
        for (int j = 0; j < 4; ++j)
            cp_async16(base + dstOff[j], bSrc[j] + k0);
        cp_commit();
    };

    // ---- ldmatrix per-lane offsets ----
    // A x4 quads: row = (q&1)*8 + rl, kbyte = (q>>1)*16  -> canonical a0..a3
    const uint32_t aLaneOff =
        (uint32_t)((warpM * 32 + (quad & 1) * 8 + rl) * ROWB + (quad >> 1) * 16);
    // B x4 quads: row(n) = (q>>1)*8 + rl, kbyte = (q&1)*16 -> [g0 k0][g0 k8][g1 k0][g1 k8]
    const uint32_t bLaneOff =
        (uint32_t)((warpN * 64 + (quad >> 1) * 8 + rl) * ROWB + (quad & 1) * 16) + TILE_BYTES;

    float acc[2][8][4];
#pragma unroll
    for (int mi = 0; mi < 2; ++mi)
#pragma unroll
        for (int ni = 0; ni < 8; ++ni)
#pragma unroll
            for (int c = 0; c < 4; ++c) acc[mi][ni][c] = 0.0f;

    // ---- prologue: 2 stages in flight ----
    issue_A(0, 0);               issue_B(0, 0);
    issue_A(STAGE_BYTES, BK);    issue_B(STAGE_BYTES, BK);

    uint32_t compOff  = 0;
    uint32_t issueOff = 2 * STAGE_BYTES;

    for (int it = 0; it < KITERS; ++it) {
        // Pending groups: stages it, it+1. wait<1> -> stage `it` arrived.
        cp_wait<1>();
        // Barrier: stage it visible; all warps done computing stage it-1
        // (its buffer (it+2)%3 is re-filled below, after this barrier).
        __syncthreads();

        const uint32_t aA = smemAddr + compOff + aLaneOff;
        const uint32_t bA = smemAddr + compOff + bLaneOff;

#pragma unroll
        for (int kk = 0; kk < 4; ++kk) {
            const int ks = (kk + rot) & 3;           // warp-parity rotated k16-chunk
            const uint32_t ko = (uint32_t)(ks * 32); // 16 halves = 32 B

            uint32_t af[2][4], bf[4][4];
            ldsm_x4(aA + ko,        af[0]);
            ldsm_x4(aA + 16 * ROWB + ko, af[1]);     // +16 rows
            ldsm_x4(bA + ko,             bf[0]);     // n-groups 0,1
            ldsm_x4(bA + 16 * ROWB + ko, bf[1]);     // n-groups 2,3
#pragma unroll
            for (int p = 0; p < 2; ++p) {
#pragma unroll
                for (int mi = 0; mi < 2; ++mi) {
                    mma_f16(acc[mi][2 * p],     af[mi], &bf[p][0]);
                    mma_f16(acc[mi][2 * p + 1], af[mi], &bf[p][2]);
                }
            }
            ldsm_x4(bA + 32 * ROWB + ko, bf[2]);     // n-groups 4,5
            ldsm_x4(bA + 48 * ROWB + ko, bf[3]);     // n-groups 6,7

            // spread cp.async issue across the iteration
            if (kk == 0 && it + 2 < KITERS) issue_A(issueOff, (it + 2) * BK);
            if (kk == 1) {
                if (it + 2 < KITERS) issue_B(issueOff, (it + 2) * BK);
                else                 cp_commit();    // keep group accounting aligned
            }

#pragma unroll
            for (int p = 2; p < 4; ++p) {
#pragma unroll
                for (int mi = 0; mi < 2; ++mi) {
                    mma_f16(acc[mi][2 * p],     af[mi], &bf[p][0]);
                    mma_f16(acc[mi][2 * p + 1], af[mi], &bf[p][2]);
                }
            }
        }

        compOff += STAGE_BYTES;  if (compOff  == DYN_SMEM) compOff  = 0;
        issueOff += STAGE_BYTES; if (issueOff == DYN_SMEM) issueOff = 0;
    }

    // ---------------- epilogue: bias + relu + store ----------------
    const float* bm_bias = bias + (size_t)m * U_DIM + colBase + warpN * 64;
#pragma unroll
    for (int mi = 0; mi < 2; ++mi) {
        const int r0 = rowBase + warpM * 32 + mi * 16 + g;
        float* o0 = out + (size_t)r0 * LDO + (size_t)m * U_DIM + colBase + warpN * 64;
        float* o1 = o0 + (size_t)8 * LDO;
#pragma unroll
        for (int ni = 0; ni < 8; ++ni) {
            const int c = ni * 8 + t * 2;
            const float b0 = bm_bias[c], b1 = bm_bias[c + 1];
            float2 v0, v1;
            v0.x = fmaxf(acc[mi][ni][0] + b0, 0.0f);
            v0.y = fmaxf(acc[mi][ni][1] + b1, 0.0f);
            v1.x = fmaxf(acc[mi][ni][2] + b0, 0.0f);
            v1.y = fmaxf(acc[mi][ni][3] + b1, 0.0f);
            *(float2*)(o0 + c) = v0;
            *(float2*)(o1 + c) = v1;
        }
    }
}

// ---------------- launch ----------------
extern "C" void kernel_launch(void* const* d_in, const int* in_sizes, int n_in,
                              void* d_out, int out_size) {
    const float* x    = (const float*)d_in[0];
    const float* W    = (const float*)d_in[1];
    const float* bias = (const float*)d_in[2];
    float* out        = (float*)d_out;

    convert_x_kernel<<<32768, 256>>>((const float4*)x);
    dim3 tg(U_DIM / 32, F_DIM / 32, M_DIM);   // (16,16,64)
    transpose_W_kernel<<<tg, dim3(32, 8)>>>(W);

    cudaFuncSetAttribute(pd_mma_f16, cudaFuncAttributeMaxDynamicSharedMemorySize, DYN_SMEM);
    dim3 grid(U_DIM / BN, B_DIM / BM, M_DIM);  // (4,16,64) = 4096 CTAs
    pd_mma_f16<<<grid, THREADS, DYN_SMEM>>>(bias, out);
}